// round 11
// baseline (speedup 1.0000x reference)
#include <cuda_runtime.h>

#define T_LEN 2048
#define B_SZ  256
#define HDIM  64
#define Y_SIZE (B_SZ * T_LEN)

typedef unsigned long long u64;

// scratch for per-(dir,batch,t) scalar projections s = h . w_fc
__device__ float g_s[2 * B_SZ * T_LEN];

__device__ __forceinline__ u64 ffma2(u64 a, u64 b, u64 c) {
    u64 d;
    asm("fma.rn.f32x2 %0, %1, %2, %3;" : "=l"(d) : "l"(a), "l"(b), "l"(c));
    return d;
}
__device__ __forceinline__ u64 fadd2(u64 a, u64 b) {
    u64 d;
    asm("add.rn.f32x2 %0, %1, %2;" : "=l"(d) : "l"(a), "l"(b));
    return d;
}
__device__ __forceinline__ u64 pack2(float lo, float hi) {
    u64 r;
    asm("mov.b64 %0, {%1, %2};" : "=l"(r) : "f"(lo), "f"(hi));
    return r;
}
__device__ __forceinline__ void unpack2(u64 v, float& lo, float& hi) {
    asm("mov.b64 {%0, %1}, %2;" : "=f"(lo), "=f"(hi) : "l"(v));
}
__device__ __forceinline__ float fast_tanh(float z) {
    // 1 - 2/(1+e^{2z}); EX2+RCP based, ~1e-7 rel err, monotone, saturates correctly
    float e = __expf(2.0f * z);
    return 1.0f - __fdividef(2.0f, e + 1.0f);
}
__device__ __forceinline__ void st_cs(float* p, float v) {
    asm volatile("st.global.cs.f32 [%0], %1;" :: "l"(p), "f"(v) : "memory");
}

__global__ __launch_bounds__(128, 1)
void birnn_kernel(const float* __restrict__ x,
                  const float* __restrict__ w_ih_f, const float* __restrict__ w_hh_f,
                  const float* __restrict__ b_ih_f, const float* __restrict__ b_hh_f,
                  const float* __restrict__ w_ih_b, const float* __restrict__ w_hh_b,
                  const float* __restrict__ b_ih_b, const float* __restrict__ b_hh_b,
                  const float* __restrict__ w_fc,  const float* __restrict__ b_fc,
                  float* __restrict__ out)
{
    __shared__ __align__(16) float xsh[2][T_LEN];        // two batch rows of x
    __shared__ __align__(16) float hbuf[4][2][HDIM];     // per-warp double-buffered h

    const int tid  = threadIdx.x;
    const int wid  = tid >> 5;        // 0..3 -> distinct SMSPs
    const int lane = tid & 31;
    const int bb   = blockIdx.x;      // 0..127
    const int bl   = wid >> 1;        // batch-local 0/1
    const int dir  = wid & 1;         // 0 fwd, 1 bwd
    const int batch = bb * 2 + bl;

    // ---- preload the two x rows into SMEM (cooperative, float4) ----
    {
        const float4* xg0 = (const float4*)(x + (bb * 2 + 0) * T_LEN);
        const float4* xg1 = (const float4*)(x + (bb * 2 + 1) * T_LEN);
        float4* xs0 = (float4*)xsh[0];
        float4* xs1 = (float4*)xsh[1];
        for (int i = tid; i < T_LEN / 4; i += 128) {
            xs0[i] = xg0[i];
            xs1[i] = xg1[i];
        }
    }

    // zero initial hidden state (buffer 0)
    hbuf[wid][0][lane]      = 0.0f;
    hbuf[wid][0][lane + 32] = 0.0f;

    // ---- per-direction parameters ----
    const float* w_ih = dir ? w_ih_b : w_ih_f;
    const float* w_hh = dir ? w_hh_b : w_hh_f;
    const float* b_ih = dir ? b_ih_b : b_ih_f;
    const float* b_hh = dir ? b_hh_b : b_hh_f;

    const int r0 = lane, r1 = lane + 32;
    const float wih0  = w_ih[r0],  wih1  = w_ih[r1];
    const float bias0 = b_ih[r0] + b_hh[r0];
    const float bias1 = b_ih[r1] + b_hh[r1];
    const float wfc0  = w_fc[r0],  wfc1  = w_fc[r1];

    // W_hh rows r0, r1 as packed f32-pairs in registers (128 regs)
    u64 Wp0[32], Wp1[32];
    {
        const u64* wr0 = (const u64*)(w_hh + r0 * HDIM);  // 256B-aligned rows
        const u64* wr1 = (const u64*)(w_hh + r1 * HDIM);
        #pragma unroll
        for (int k = 0; k < 32; k++) { Wp0[k] = wr0[k]; Wp1[k] = wr1[k]; }
    }

    float* g_row = g_s + (dir * B_SZ + batch) * T_LEN;
    const float* xrow = xsh[bl];

    __syncthreads();   // x preload + h init visible

    float h0 = 0.0f, h1 = 0.0f;
    float pr_prev = 0.0f;          // previous step's un-reduced w_fc partial
    int   t_prev  = 0;

    #pragma unroll 1
    for (int s = 0; s < T_LEN; s++) {
        const int t = dir ? (T_LEN - 1 - s) : s;
        const float xt = xrow[t];
        const int p = s & 1;
        const ulonglong2* hv = (const ulonglong2*)hbuf[wid][p];

        // accumulators: xp folded into a-chain; 4 chains of depth 16
        u64 a0 = pack2(fmaf(xt, wih0, bias0), 0.0f);
        u64 a1 = pack2(fmaf(xt, wih1, bias1), 0.0f);
        u64 c0 = 0ULL;  // {0,0}
        u64 c1 = 0ULL;

        #pragma unroll
        for (int k = 0; k < 16; k++) {
            const ulonglong2 h2 = hv[k];       // broadcast LDS.128
            a0 = ffma2(Wp0[2 * k],     h2.x, a0);
            c0 = ffma2(Wp0[2 * k + 1], h2.y, c0);
            a1 = ffma2(Wp1[2 * k],     h2.x, a1);
            c1 = ffma2(Wp1[2 * k + 1], h2.y, c1);
        }

        // ---- pipelined reduction of PREVIOUS step's partial (off critical path) ----
        float red = pr_prev;
        #pragma unroll
        for (int o = 16; o; o >>= 1) red += __shfl_xor_sync(0xffffffffu, red, o);
        if (lane == 0 && s > 0) st_cs(&g_row[t_prev], red);

        float lo, hi;
        u64 d0 = fadd2(a0, c0); unpack2(d0, lo, hi); const float z0 = lo + hi;
        u64 d1 = fadd2(a1, c1); unpack2(d1, lo, hi); const float z1 = lo + hi;

        h0 = fast_tanh(z0);
        h1 = fast_tanh(z1);

        float* hw = hbuf[wid][p ^ 1];
        hw[r0] = h0;
        hw[r1] = h1;

        pr_prev = fmaf(h1, wfc1, h0 * wfc0);
        t_prev  = t;

        __syncwarp();
    }

    // flush final step's reduction
    {
        float red = pr_prev;
        #pragma unroll
        for (int o = 16; o; o >>= 1) red += __shfl_xor_sync(0xffffffffu, red, o);
        if (lane == 0) st_cs(&g_row[t_prev], red);
    }

    // final hidden states: h_n[dir][batch][i]
    out[Y_SIZE + dir * (B_SZ * HDIM) + batch * HDIM + r0] = h0;
    out[Y_SIZE + dir * (B_SZ * HDIM) + batch * HDIM + r1] = h1;

    __syncthreads();   // CTA-scope: g_s writes from all 4 warps visible

    // ---- epilogue: y[b][t] = sigmoid(0.5*(s_f+s_b) + b_fc) ----
    const float bfc = b_fc[0];
    for (int m = tid; m < 2 * T_LEN; m += 128) {
        const int blc = m >> 11;           // T_LEN == 2048
        const int t   = m & (T_LEN - 1);
        const int bg  = bb * 2 + blc;
        const float sf = g_s[(0 * B_SZ + bg) * T_LEN + t];
        const float sb = g_s[(1 * B_SZ + bg) * T_LEN + t];
        const float sv = 0.5f * (sf + sb) + bfc;
        out[bg * T_LEN + t] = __fdividef(1.0f, 1.0f + __expf(-sv));
    }
}

extern "C" void kernel_launch(void* const* d_in, const int* in_sizes, int n_in,
                              void* d_out, int out_size) {
    birnn_kernel<<<128, 128>>>(
        (const float*)d_in[0],                         // x [B,T,1]
        (const float*)d_in[1], (const float*)d_in[2],  // w_ih_f, w_hh_f
        (const float*)d_in[3], (const float*)d_in[4],  // b_ih_f, b_hh_f
        (const float*)d_in[5], (const float*)d_in[6],  // w_ih_b, w_hh_b
        (const float*)d_in[7], (const float*)d_in[8],  // b_ih_b, b_hh_b
        (const float*)d_in[9], (const float*)d_in[10], // w_fc, b_fc
        (float*)d_out);
}